// round 10
// baseline (speedup 1.0000x reference)
#include <cuda_runtime.h>
#include <cstdint>

#define Bq 128
#define Tq 512
#define TAGq 256
#define START_TAG 254
#define STOP_TAG 255
#define NT 512

// Scratch (allocation-free rule: static __device__ globals)
__device__ float g_hist[(size_t)Bq * Tq * TAGq];   // partition history, 64 MB
__device__ float g_transT[TAGq * TAGq];            // transposed transitions

__device__ __forceinline__ float2 fadd2_(float2 a, float2 b) {
    float2 o;
    asm("{\n\t"
        ".reg .b64 ra, rb, rc;\n\t"
        "mov.b64 ra, {%2,%3};\n\t"
        "mov.b64 rb, {%4,%5};\n\t"
        "add.rn.f32x2 rc, ra, rb;\n\t"
        "mov.b64 {%0,%1}, rc;\n\t"
        "}"
        : "=f"(o.x), "=f"(o.y)
        : "f"(a.x), "f"(a.y), "f"(b.x), "f"(b.y));
    return o;
}

__device__ __forceinline__ float neg_inf() { return __int_as_float(0xff800000u); }

// Strictly order-preserving float -> u32 key (finite values, no NaN here).
__device__ __forceinline__ unsigned okey(float f) {
    unsigned u = __float_as_uint(f);
    return (u & 0x80000000u) ? ~u : (u | 0x80000000u);
}

__device__ __forceinline__ unsigned smem_u32(const void* p) {
    return (unsigned)__cvta_generic_to_shared(p);
}

// ---------------------------------------------------------------------------
// transT[t2][j] = trans[j][t2]
__global__ void transpose_kernel(const float* __restrict__ trans) {
    int j  = blockIdx.x;
    int t2 = threadIdx.x;
    g_transT[t2 * TAGq + j] = trans[j * TAGq + t2];
}

// ---------------------------------------------------------------------------
// Forward Viterbi, cluster-of-2 version. Grid = 128 CTAs = 64 clusters.
// Cluster c serves batches (2c, 2c+1). CTA rank r reduces j in
// [r*128, r*128+128); thread (t2 = tid&255, half = tid>>8) holds its 64-j
// trans slice ENTIRELY in registers -> zero trans SMEM traffic in the loop.
// Each CTA keeps the combined partition values for tags in its own range;
// partials for the peer's tag range are pushed over DSMEM each step.
__global__ __launch_bounds__(NT, 1) __cluster_dims__(2, 1, 1)
void forward_kernel(const float* __restrict__ feats,
                    const float* __restrict__ trans) {
    __shared__ float part[2][2][TAGq];      // [batch][buf][tag] (only my range used)
    __shared__ float partial[2][NT];        // [batch][tid]
    __shared__ float theirs[2][2][128];     // [parity][batch][local tag]
    __shared__ __align__(8) unsigned long long mbar;

    const int tid  = threadIdx.x;
    const int t2   = tid & 255;
    const int half = tid >> 8;

    unsigned rank;
    asm("mov.u32 %0, %%cluster_ctarank;" : "=r"(rank));
    const unsigned peer = rank ^ 1u;

    const int b0 = (int)(blockIdx.x & ~1u);   // cluster base = batch 0
    const int b1 = b0 + 1;
    const int my_base   = (int)rank * 128;    // my tag/j range start
    const int peer_base = (int)peer * 128;
    const int jbase = my_base + half * 64;

    // Register-resident trans slice: transT[t2][jbase .. jbase+64)
    float4 tr4[16];
    {
        const float4* src = (const float4*)(g_transT + (size_t)t2 * TAGq + jbase);
        #pragma unroll
        for (int k = 0; k < 16; ++k) tr4[k] = src[k];
    }

    const float* fe0 = feats + (size_t)b0 * Tq * TAGq;
    const float* fe1 = feats + (size_t)b1 * Tq * TAGq;
    float* hb0 = g_hist + (size_t)b0 * Tq * TAGq;
    float* hb1 = g_hist + (size_t)b1 * Tq * TAGq;

    if (tid == 0) {
        unsigned a = smem_u32(&mbar);
        asm volatile("mbarrier.init.shared.b64 [%0], %1;"
                     :: "r"(a), "r"(256u) : "memory");
    }

    const bool mine = (tid < TAGq) && (t2 >= my_base) && (t2 < my_base + 128);

    // part0 = feats[b,0,:] + trans[START,:]  (my tag range only)
    if (mine) {
        float ts  = trans[START_TAG * TAGq + t2];
        float p00 = fe0[t2] + ts;
        float p01 = fe1[t2] + ts;
        part[0][0][t2] = p00;
        part[1][0][t2] = p01;
        hb0[t2] = p00;
        hb1[t2] = p01;
    }

    // prefetch emissions for t = 1
    float e0 = __ldg(fe0 + TAGq + t2);
    float e1 = __ldg(fe1 + TAGq + t2);

    __syncthreads();
    // both CTAs' mbarrier init + part init complete before any remote traffic
    asm volatile("barrier.cluster.arrive.aligned;" ::: "memory");
    asm volatile("barrier.cluster.wait.aligned;" ::: "memory");

    const unsigned mbar_local = smem_u32(&mbar);
    unsigned mbar_remote;
    asm("mapa.shared::cluster.u32 %0, %1, %2;"
        : "=r"(mbar_remote) : "r"(mbar_local), "r"(peer));

    // Precompute remote store addresses (threads whose tag is in PEER range
    // push their combined-halves partial to peer's theirs[par][batch][x]).
    unsigned rth[2][2] = {{0u, 0u}, {0u, 0u}};   // [parity][batch]
    const bool pushes = (tid < TAGq) && !mine;
    if (pushes) {
        int x = t2 - peer_base;
        #pragma unroll
        for (int p = 0; p < 2; ++p)
            #pragma unroll
            for (int bb = 0; bb < 2; ++bb) {
                unsigned la = smem_u32(&theirs[p][bb][x]);
                asm("mapa.shared::cluster.u32 %0, %1, %2;"
                    : "=r"(rth[p][bb]) : "r"(la), "r"(peer));
            }
    }

    int cb = 0;
    unsigned par = 0;

    for (int t = 1; t < Tq; ++t) {
        // prefetch next step's emissions (one full step of latency slack)
        const int tn = (t + 1 < Tq) ? (t + 1) : t;
        float e0n = __ldg(fe0 + (size_t)tn * TAGq + t2);
        float e1n = __ldg(fe1 + (size_t)tn * TAGq + t2);

        const float2 e02 = make_float2(e0, e0);
        const float2 e12 = make_float2(e1, e1);
        const float4* p0 = (const float4*)&part[0][cb][jbase];  // broadcast
        const float4* p1 = (const float4*)&part[1][cb][jbase];  // broadcast

        float m00 = neg_inf(), m01 = m00, m02 = m00, m03 = m00;
        float m10 = m00, m11 = m00, m12 = m00, m13 = m00;

        #pragma unroll
        for (int k = 0; k < 16; ++k) {
            float4 ta = tr4[k];
            float4 pa = p0[k];
            float4 pb = p1[k];
            float2 s;
            // exact reference order: (emit + trans) + part
            s = fadd2_(fadd2_(e02, make_float2(ta.x, ta.y)), make_float2(pa.x, pa.y));
            m00 = fmaxf(m00, s.x); m01 = fmaxf(m01, s.y);
            s = fadd2_(fadd2_(e02, make_float2(ta.z, ta.w)), make_float2(pa.z, pa.w));
            m02 = fmaxf(m02, s.x); m03 = fmaxf(m03, s.y);
            s = fadd2_(fadd2_(e12, make_float2(ta.x, ta.y)), make_float2(pb.x, pb.y));
            m10 = fmaxf(m10, s.x); m11 = fmaxf(m11, s.y);
            s = fadd2_(fadd2_(e12, make_float2(ta.z, ta.w)), make_float2(pb.z, pb.w));
            m12 = fmaxf(m12, s.x); m13 = fmaxf(m13, s.y);
        }
        partial[0][tid] = fmaxf(fmaxf(m00, m01), fmaxf(m02, m03));
        partial[1][tid] = fmaxf(fmaxf(m10, m11), fmaxf(m12, m13));
        __syncthreads();

        if (tid < TAGq) {
            // combine the two thread-halves of this CTA for tag t2
            float v0 = fmaxf(partial[0][t2], partial[0][t2 + 256]);
            float v1 = fmaxf(partial[1][t2], partial[1][t2 + 256]);

            if (pushes) {
                // my tag belongs to peer: ship the partial over DSMEM
                asm volatile("st.shared::cluster.b32 [%0], %1;"
                             :: "r"(rth[par][0]), "r"(__float_as_uint(v0)) : "memory");
                asm volatile("st.shared::cluster.b32 [%0], %1;"
                             :: "r"(rth[par][1]), "r"(__float_as_uint(v1)) : "memory");
            }
            // release my stores, then arrive on PEER's barrier
            asm volatile("fence.acq_rel.cluster;" ::: "memory");
            asm volatile("mbarrier.arrive.shared::cluster.b64 _, [%0];"
                         :: "r"(mbar_remote) : "memory");

            // wait for peer's 256 arrivals on MY barrier (parity-phased)
            unsigned done = 0;
            do {
                asm volatile(
                    "{\n\t.reg .pred p;\n\t"
                    "mbarrier.try_wait.parity.acquire.cta.shared::cta.b64 p, [%1], %2, 0x989680;\n\t"
                    "selp.b32 %0, 1, 0, p;\n\t}"
                    : "=r"(done) : "r"(mbar_local), "r"(par) : "memory");
            } while (!done);
            asm volatile("fence.acq_rel.cluster;" ::: "memory");

            if (mine) {
                int x = t2 - my_base;
                float f0 = fmaxf(v0, theirs[par][0][x]);
                float f1 = fmaxf(v1, theirs[par][1][x]);
                part[0][cb ^ 1][t2] = f0;
                part[1][cb ^ 1][t2] = f1;
                hb0[(size_t)t * TAGq + t2] = f0;
                hb1[(size_t)t * TAGq + t2] = f1;
            }
        }
        __syncthreads();
        cb ^= 1;
        par ^= 1u;
        e0 = e0n;
        e1 = e1n;
    }

    // no CTA may exit while the peer could still touch this CTA's SMEM
    asm volatile("barrier.cluster.arrive.aligned;" ::: "memory");
    asm volatile("barrier.cluster.wait.aligned;" ::: "memory");
}

// ---------------------------------------------------------------------------
// Warp argmax over 256 contiguous values (8 per lane, ascending j), with
// jnp.argmax first-index semantics: lane-local strict-greater ascending scan,
// then redux-max on an order-preserving key; lowest matching lane wins ties.
__device__ __forceinline__ int warp_argmax256(float xv, int xi, float* vmax_out) {
    unsigned kk   = okey(xv);
    unsigned kmax = __reduce_max_sync(0xffffffffu, kk);
    unsigned bal  = __ballot_sync(0xffffffffu, kk == kmax);
    int src = __ffs((int)bal) - 1;
    if (vmax_out)
        *vmax_out = __shfl_sync(0xffffffffu, xv, src);
    return __shfl_sync(0xffffffffu, xi, src);
}

// One warp per batch: final score + full backtrace with bp recomputation.
__global__ void backward_kernel(const float* __restrict__ feats,
                                const int*   __restrict__ mask,
                                float*       __restrict__ out) {
    const int b = blockIdx.x, lane = threadIdx.x;

    // lengths = sum(mask[b,:])  (also warms the mask row into L1)
    int len = 0;
    for (int i = lane; i < Tq; i += 32) len += mask[b * Tq + i];
    #pragma unroll
    for (int o = 16; o; o >>= 1) len += __shfl_down_sync(0xffffffffu, len, o);
    len = __shfl_sync(0xffffffffu, len, 0);
    const int last = len - 1;

    const float* hb = g_hist + (size_t)b * Tq * TAGq;

    // path score / pointer: argmax_j last_part[j] + trans[j][STOP]
    int ptr;
    {
        const float4* lp4 = (const float4*)(hb + (size_t)last * TAGq) + lane * 2;
        const float4* tc4 = (const float4*)(g_transT + STOP_TAG * TAGq) + lane * 2;
        float4 A = lp4[0], B = lp4[1], C = tc4[0], D = tc4[1];
        float v[8] = {A.x + C.x, A.y + C.y, A.z + C.z, A.w + C.w,
                      B.x + D.x, B.y + D.y, B.z + D.z, B.w + D.w};
        float xv = v[0]; int xi = lane * 8;
        #pragma unroll
        for (int k = 1; k < 8; ++k)
            if (v[k] > xv) { xv = v[k]; xi = lane * 8 + k; }
        float bv;
        ptr = warp_argmax256(xv, xi, &bv);
        if (lane == 0) out[b] = bv;
    }

    float* dec = out + Bq;
    if (lane == 0) dec[(size_t)b * Tq + (Tq - 1)] = (float)ptr;

    int cur = ptr;
    for (int i = Tq - 2; i >= 0; --i) {
        // Prefetch-touch rows needed at iteration i-1 (index-predictable,
        // independent of cur): feats[b, i, :] and hist[b, i-1, :].
        {
            float d0;
            const float* fr = feats + ((size_t)b * Tq + i) * TAGq + lane * 8;
            asm volatile("ld.global.nc.f32 %0, [%1];" : "=f"(d0) : "l"(fr));
            if (i >= 1) {
                float d1;
                const float* hr = hb + (size_t)(i - 1) * TAGq + lane * 8;
                asm volatile("ld.global.nc.f32 %0, [%1];" : "=f"(d1) : "l"(hr));
            }
        }

        int nv;
        if (i == last) {
            nv = ptr;
        } else if (mask[b * Tq + i + 1] == 0) {
            nv = 0;
        } else {
            // recompute bp at time i+1, column cur — identical arithmetic
            // to the forward pass: (emit + trans) + part
            const float e =
                __ldg(feats + ((size_t)b * Tq + (i + 1)) * TAGq + cur);
            const float4* h4 = (const float4*)(hb + (size_t)i * TAGq) + lane * 2;
            const float4* t4 =
                (const float4*)(g_transT + (size_t)cur * TAGq) + lane * 2;
            float4 H0 = h4[0], H1 = h4[1], T0 = t4[0], T1 = t4[1];
            float v[8] = {(e + T0.x) + H0.x, (e + T0.y) + H0.y,
                          (e + T0.z) + H0.z, (e + T0.w) + H0.w,
                          (e + T1.x) + H1.x, (e + T1.y) + H1.y,
                          (e + T1.z) + H1.z, (e + T1.w) + H1.w};
            float xv = v[0]; int xi = lane * 8;
            #pragma unroll
            for (int k = 1; k < 8; ++k)
                if (v[k] > xv) { xv = v[k]; xi = lane * 8 + k; }
            nv = warp_argmax256(xv, xi, nullptr);
        }
        cur = nv;
        if (lane == 0) dec[(size_t)b * Tq + i] = (float)cur;
    }
}

// ---------------------------------------------------------------------------
extern "C" void kernel_launch(void* const* d_in, const int* in_sizes, int n_in,
                              void* d_out, int out_size) {
    const float* feats = (const float*)d_in[0];   // (128,512,256) f32
    const int*   mask  = (const int*)d_in[1];     // (128,512) i32
    const float* trans = (const float*)d_in[2];   // (256,256) f32
    float* out = (float*)d_out;                   // [128 path_score | 128*512 decode]

    transpose_kernel<<<TAGq, TAGq>>>(trans);

    forward_kernel<<<Bq, NT>>>(feats, trans);    // 128 CTAs = 64 clusters of 2

    backward_kernel<<<Bq, 32>>>(feats, mask, out);
}

// round 11
// speedup vs baseline: 1.2992x; 1.2992x over previous
#include <cuda_runtime.h>
#include <cstdint>

#define Bq 128
#define Tq 512
#define TAGq 256
#define START_TAG 254
#define STOP_TAG 255
#define NTHREADS 512       // 2-way j-split: tid = half*256 + t2
#define TSTRIDE 68         // floats per tile row = 17 float4 (68 mod 32 = 4 -> conflict-free)

// Scratch (allocation-free rule: static __device__ globals)
__device__ float g_hist[(size_t)Bq * Tq * TAGq];   // partition history, 64 MB
__device__ float g_transT[TAGq * TAGq];            // transposed transitions

__device__ __forceinline__ float2 fadd2_(float2 a, float2 b) {
    float2 o;
    asm("{\n\t"
        ".reg .b64 ra, rb, rc;\n\t"
        "mov.b64 ra, {%2,%3};\n\t"
        "mov.b64 rb, {%4,%5};\n\t"
        "add.rn.f32x2 rc, ra, rb;\n\t"
        "mov.b64 {%0,%1}, rc;\n\t"
        "}"
        : "=f"(o.x), "=f"(o.y)
        : "f"(a.x), "f"(a.y), "f"(b.x), "f"(b.y));
    return o;
}

__device__ __forceinline__ float neg_inf() { return __int_as_float(0xff800000u); }

// Strictly order-preserving float -> u32 key (finite values, no NaN here).
__device__ __forceinline__ unsigned okey(float f) {
    unsigned u = __float_as_uint(f);
    return (u & 0x80000000u) ? ~u : (u | 0x80000000u);
}

// ---------------------------------------------------------------------------
// transT[t2][j] = trans[j][t2]
__global__ void transpose_kernel(const float* __restrict__ trans) {
    int j  = blockIdx.x;
    int t2 = threadIdx.x;
    g_transT[t2 * TAGq + j] = trans[j * TAGq + t2];
}

// ---------------------------------------------------------------------------
// Forward Viterbi: one CTA per batch, 512 threads.
// Thread (half = tid>>8, t2 = tid&255) reduces j in [half*128, half*128+128).
// trans[j..j+96)    -> 24 float4 REGISTERS (loop-invariant, loaded once)
// trans[j+96..128)  -> SMEM tile (compacted: 32 cols per (row,half), stride 68)
// part[]            -> SMEM, warp-broadcast loads (half uniform per warp)
__global__ __launch_bounds__(NTHREADS, 1)
void forward_kernel(const float* __restrict__ feats,
                    const float* __restrict__ trans) {
    extern __shared__ float smem_f[];
    float* tile    = smem_f;                        // [256][TSTRIDE]
    float* partA   = smem_f + TAGq * TSTRIDE;       // 256
    float* partB   = partA + TAGq;                  // 256
    float* partial = partB + TAGq;                  // 512

    const int b    = blockIdx.x;
    const int tid  = threadIdx.x;
    const int t2   = tid & 255;
    const int half = tid >> 8;

    // Stage compacted tile:
    //   tile[r] f4 [0,8)  = transT[r] f4 [24,32)  (orig cols  96..127, for half 0)
    //   tile[r] f4 [8,16) = transT[r] f4 [56,64)  (orig cols 224..255, for half 1)
    for (int idx = tid; idx < TAGq * 16; idx += NTHREADS) {
        int r = idx >> 4, c4 = idx & 15;
        int src4 = (c4 < 8) ? (c4 + 24) : (c4 + 48);
        ((float4*)(tile + r * TSTRIDE))[c4] =
            ((const float4*)g_transT)[r * 64 + src4];
    }

    // Register-resident trans slice: transT[t2][half*128 .. half*128+96)
    float4 tr4[24];
    {
        const float4* src = (const float4*)(g_transT + (size_t)t2 * TAGq) + half * 32;
        #pragma unroll
        for (int k = 0; k < 24; ++k) tr4[k] = src[k];
    }

    const float* febase = feats + (size_t)b * Tq * TAGq;
    float*       hbase  = g_hist + (size_t)b * Tq * TAGq;

    // part0 = feats[b,0,:] + trans[START,:]
    if (tid < TAGq) {
        float p0 = febase[tid] + trans[START_TAG * TAGq + tid];
        partA[tid] = p0;
        hbase[tid] = p0;
    }

    // prefetch emission for t = 1
    float e = __ldcs(febase + (size_t)TAGq + t2);
    __syncthreads();

    const float4* trow_s = (const float4*)(tile + t2 * TSTRIDE) + half * 8;

    float* cur = partA;
    float* nxt = partB;

    for (int t = 1; t < Tq; ++t) {
        // prefetch next step's emission (one full step of latency slack)
        const int tn = (t + 1 < Tq) ? (t + 1) : t;
        float e_nxt = __ldcs(febase + (size_t)tn * TAGq + t2);

        const float2 e2 = make_float2(e, e);
        const float4* p4 = (const float4*)cur + half * 32;  // warp-broadcast

        float a0 = neg_inf(), a1 = a0, a2 = a0, a3 = a0;
        float a4 = a0, a5 = a0, a6 = a0, a7 = a0;

        // j local [0,96): trans from registers
        #pragma unroll
        for (int k = 0; k < 24; ++k) {
            float4 pa = p4[k];
            float4 ta = tr4[k];
            float2 s;
            s = fadd2_(fadd2_(e2, make_float2(ta.x, ta.y)), make_float2(pa.x, pa.y));
            a0 = fmaxf(a0, s.x); a1 = fmaxf(a1, s.y);
            s = fadd2_(fadd2_(e2, make_float2(ta.z, ta.w)), make_float2(pa.z, pa.w));
            a2 = fmaxf(a2, s.x); a3 = fmaxf(a3, s.y);
        }
        // j local [96,128): trans from SMEM tile
        #pragma unroll
        for (int k = 0; k < 8; ++k) {
            float4 pb = p4[24 + k];
            float4 tb = trow_s[k];
            float2 s;
            s = fadd2_(fadd2_(e2, make_float2(tb.x, tb.y)), make_float2(pb.x, pb.y));
            a4 = fmaxf(a4, s.x); a5 = fmaxf(a5, s.y);
            s = fadd2_(fadd2_(e2, make_float2(tb.z, tb.w)), make_float2(pb.z, pb.w));
            a6 = fmaxf(a6, s.x); a7 = fmaxf(a7, s.y);
        }
        float m = fmaxf(fmaxf(fmaxf(a0, a1), fmaxf(a2, a3)),
                        fmaxf(fmaxf(a4, a5), fmaxf(a6, a7)));

        partial[tid] = m;
        __syncthreads();

        if (tid < TAGq) {
            float mm = fmaxf(partial[tid], partial[tid + TAGq]);
            nxt[tid] = mm;
            hbase[(size_t)t * TAGq + tid] = mm;
        }
        __syncthreads();

        float* tp = cur; cur = nxt; nxt = tp;
        e = e_nxt;
    }
}

// ---------------------------------------------------------------------------
// Warp argmax over 256 contiguous values (8 per lane, ascending j), with
// jnp.argmax first-index semantics: lane-local strict-greater ascending scan,
// then redux-max on an order-preserving key; lowest matching lane wins ties.
__device__ __forceinline__ int warp_argmax256(float xv, int xi, float* vmax_out) {
    unsigned kk   = okey(xv);
    unsigned kmax = __reduce_max_sync(0xffffffffu, kk);
    unsigned bal  = __ballot_sync(0xffffffffu, kk == kmax);
    int src = __ffs((int)bal) - 1;
    if (vmax_out)
        *vmax_out = __shfl_sync(0xffffffffu, xv, src);
    return __shfl_sync(0xffffffffu, xi, src);
}

// One warp per batch: final score + full backtrace with bp recomputation.
__global__ void backward_kernel(const float* __restrict__ feats,
                                const int*   __restrict__ mask,
                                float*       __restrict__ out) {
    const int b = blockIdx.x, lane = threadIdx.x;

    // lengths = sum(mask[b,:])  (also warms the mask row into L1)
    int len = 0;
    for (int i = lane; i < Tq; i += 32) len += mask[b * Tq + i];
    #pragma unroll
    for (int o = 16; o; o >>= 1) len += __shfl_down_sync(0xffffffffu, len, o);
    len = __shfl_sync(0xffffffffu, len, 0);
    const int last = len - 1;

    const float* hb = g_hist + (size_t)b * Tq * TAGq;

    // path score / pointer: argmax_j last_part[j] + trans[j][STOP]
    int ptr;
    {
        const float4* lp4 = (const float4*)(hb + (size_t)last * TAGq) + lane * 2;
        const float4* tc4 = (const float4*)(g_transT + STOP_TAG * TAGq) + lane * 2;
        float4 A = lp4[0], B = lp4[1], C = tc4[0], D = tc4[1];
        float v[8] = {A.x + C.x, A.y + C.y, A.z + C.z, A.w + C.w,
                      B.x + D.x, B.y + D.y, B.z + D.z, B.w + D.w};
        float xv = v[0]; int xi = lane * 8;
        #pragma unroll
        for (int k = 1; k < 8; ++k)
            if (v[k] > xv) { xv = v[k]; xi = lane * 8 + k; }
        float bv;
        ptr = warp_argmax256(xv, xi, &bv);
        if (lane == 0) out[b] = bv;
    }

    float* dec = out + Bq;
    if (lane == 0) dec[(size_t)b * Tq + (Tq - 1)] = (float)ptr;

    int cur = ptr;
    for (int i = Tq - 2; i >= 0; --i) {
        // Prefetch-touch rows needed at iteration i-1 (index-predictable,
        // independent of cur): feats[b, i, :] and hist[b, i-1, :].
        // 32 lanes x stride-8 floats = one touch per 32B sector of each 1KB row.
        {
            float d0;
            const float* fr = feats + ((size_t)b * Tq + i) * TAGq + lane * 8;
            asm volatile("ld.global.nc.f32 %0, [%1];" : "=f"(d0) : "l"(fr));
            if (i >= 1) {
                float d1;
                const float* hr = hb + (size_t)(i - 1) * TAGq + lane * 8;
                asm volatile("ld.global.nc.f32 %0, [%1];" : "=f"(d1) : "l"(hr));
            }
        }

        int nv;
        if (i == last) {
            nv = ptr;
        } else if (mask[b * Tq + i + 1] == 0) {
            nv = 0;
        } else {
            // recompute bp at time i+1, column cur — identical arithmetic
            // to the forward pass: (emit + trans) + part
            const float e =
                __ldg(feats + ((size_t)b * Tq + (i + 1)) * TAGq + cur);
            const float4* h4 = (const float4*)(hb + (size_t)i * TAGq) + lane * 2;
            const float4* t4 =
                (const float4*)(g_transT + (size_t)cur * TAGq) + lane * 2;
            float4 H0 = h4[0], H1 = h4[1], T0 = t4[0], T1 = t4[1];
            float v[8] = {(e + T0.x) + H0.x, (e + T0.y) + H0.y,
                          (e + T0.z) + H0.z, (e + T0.w) + H0.w,
                          (e + T1.x) + H1.x, (e + T1.y) + H1.y,
                          (e + T1.z) + H1.z, (e + T1.w) + H1.w};
            float xv = v[0]; int xi = lane * 8;
            #pragma unroll
            for (int k = 1; k < 8; ++k)
                if (v[k] > xv) { xv = v[k]; xi = lane * 8 + k; }
            nv = warp_argmax256(xv, xi, nullptr);
        }
        cur = nv;
        if (lane == 0) dec[(size_t)b * Tq + i] = (float)cur;
    }
}

// ---------------------------------------------------------------------------
extern "C" void kernel_launch(void* const* d_in, const int* in_sizes, int n_in,
                              void* d_out, int out_size) {
    const float* feats = (const float*)d_in[0];   // (128,512,256) f32
    const int*   mask  = (const int*)d_in[1];     // (128,512) i32
    const float* trans = (const float*)d_in[2];   // (256,256) f32
    float* out = (float*)d_out;                   // [128 path_score | 128*512 decode]

    transpose_kernel<<<TAGq, TAGq>>>(trans);

    const size_t smem =
        (size_t)(TAGq * TSTRIDE + 2 * TAGq + NTHREADS) * sizeof(float); // 73728 B
    cudaFuncSetAttribute(forward_kernel,
                         cudaFuncAttributeMaxDynamicSharedMemorySize, (int)smem);
    forward_kernel<<<Bq, NTHREADS, smem>>>(feats, trans);

    backward_kernel<<<Bq, 32>>>(feats, mask, out);
}

// round 12
// speedup vs baseline: 1.3635x; 1.0495x over previous
#include <cuda_runtime.h>
#include <cstdint>

#define Bq 128
#define Tq 512
#define TAGq 256
#define START_TAG 254
#define STOP_TAG 255
#define NTHREADS 512       // 2-way j-split: tid = half*256 + t2
#define TSTRIDE 132        // floats per tile row = 33 float4 (conflict-free .128)
#define CROWS 224          // transT rows cached in backward SMEM

// Scratch (allocation-free rule: static __device__ globals)
__device__ float g_hist[(size_t)Bq * Tq * TAGq];   // partition history, 64 MB
__device__ float g_transT[TAGq * TAGq];            // transposed transitions

__device__ __forceinline__ float2 fadd2_(float2 a, float2 b) {
    float2 o;
    asm("{\n\t"
        ".reg .b64 ra, rb, rc;\n\t"
        "mov.b64 ra, {%2,%3};\n\t"
        "mov.b64 rb, {%4,%5};\n\t"
        "add.rn.f32x2 rc, ra, rb;\n\t"
        "mov.b64 {%0,%1}, rc;\n\t"
        "}"
        : "=f"(o.x), "=f"(o.y)
        : "f"(a.x), "f"(a.y), "f"(b.x), "f"(b.y));
    return o;
}

__device__ __forceinline__ float neg_inf() { return __int_as_float(0xff800000u); }

// Strictly order-preserving float -> u32 key (finite values, no NaN here).
__device__ __forceinline__ unsigned okey(float f) {
    unsigned u = __float_as_uint(f);
    return (u & 0x80000000u) ? ~u : (u | 0x80000000u);
}
__device__ __forceinline__ float okey_dec(unsigned k) {
    unsigned u = (k & 0x80000000u) ? (k & 0x7fffffffu) : ~k;
    return __uint_as_float(u);
}

// ---------------------------------------------------------------------------
// transT[t2][j] = trans[j][t2]
__global__ void transpose_kernel(const float* __restrict__ trans) {
    int j  = blockIdx.x;
    int t2 = threadIdx.x;
    g_transT[t2 * TAGq + j] = trans[j * TAGq + t2];
}

// ---------------------------------------------------------------------------
// Forward Viterbi (measured-good R8 structure, byte-identical): one CTA per
// batch, 512 threads. Thread (half = tid>>8, t2 = tid&255) reduces j in
// [half*128, half*128+128).
__global__ __launch_bounds__(NTHREADS, 1)
void forward_kernel(const float* __restrict__ feats,
                    const float* __restrict__ trans) {
    extern __shared__ float smem_f[];
    float* tile    = smem_f;                        // [256][TSTRIDE]
    float* partA   = smem_f + TAGq * TSTRIDE;       // 256
    float* partB   = partA + TAGq;                  // 256
    float* partial = partB + TAGq;                  // 512

    const int b    = blockIdx.x;
    const int tid  = threadIdx.x;
    const int t2   = tid & 255;
    const int half = tid >> 8;

    for (int idx = tid; idx < TAGq * 32; idx += NTHREADS) {
        int r = idx >> 5, c4 = idx & 31;
        int src4 = (c4 < 16) ? (c4 + 16) : (c4 + 32);
        ((float4*)(tile + r * TSTRIDE))[c4] =
            ((const float4*)g_transT)[r * 64 + src4];
    }

    float4 tr4[16];
    {
        const float4* src = (const float4*)(g_transT + (size_t)t2 * TAGq) + half * 32;
        #pragma unroll
        for (int k = 0; k < 16; ++k) tr4[k] = src[k];
    }

    const float* febase = feats + (size_t)b * Tq * TAGq;
    float*       hbase  = g_hist + (size_t)b * Tq * TAGq;

    if (tid < TAGq) {
        float p0 = febase[tid] + trans[START_TAG * TAGq + tid];
        partA[tid] = p0;
        hbase[tid] = p0;
    }

    float e = __ldcs(febase + (size_t)TAGq + t2);
    __syncthreads();

    const float4* trow_s = (const float4*)(tile + t2 * TSTRIDE) + half * 16;

    float* cur = partA;
    float* nxt = partB;

    for (int t = 1; t < Tq; ++t) {
        const int tn = (t + 1 < Tq) ? (t + 1) : t;
        float e_nxt = __ldcs(febase + (size_t)tn * TAGq + t2);

        const float2 e2 = make_float2(e, e);
        const float4* p4 = (const float4*)cur + half * 32;  // warp-broadcast

        float a0 = neg_inf(), a1 = a0, a2 = a0, a3 = a0;
        float a4 = a0, a5 = a0, a6 = a0, a7 = a0;

        #pragma unroll
        for (int k = 0; k < 16; ++k) {
            float4 pa = p4[k];
            float4 ta = tr4[k];
            float2 s;
            s = fadd2_(fadd2_(e2, make_float2(ta.x, ta.y)), make_float2(pa.x, pa.y));
            a0 = fmaxf(a0, s.x); a1 = fmaxf(a1, s.y);
            s = fadd2_(fadd2_(e2, make_float2(ta.z, ta.w)), make_float2(pa.z, pa.w));
            a2 = fmaxf(a2, s.x); a3 = fmaxf(a3, s.y);
        }
        #pragma unroll
        for (int k = 0; k < 16; ++k) {
            float4 pb = p4[16 + k];
            float4 tb = trow_s[k];
            float2 s;
            s = fadd2_(fadd2_(e2, make_float2(tb.x, tb.y)), make_float2(pb.x, pb.y));
            a4 = fmaxf(a4, s.x); a5 = fmaxf(a5, s.y);
            s = fadd2_(fadd2_(e2, make_float2(tb.z, tb.w)), make_float2(pb.z, pb.w));
            a6 = fmaxf(a6, s.x); a7 = fmaxf(a7, s.y);
        }
        float m = fmaxf(fmaxf(fmaxf(a0, a1), fmaxf(a2, a3)),
                        fmaxf(fmaxf(a4, a5), fmaxf(a6, a7)));

        partial[tid] = m;
        __syncthreads();

        if (tid < TAGq) {
            float mm = fmaxf(partial[tid], partial[tid + TAGq]);
            nxt[tid] = mm;
            hbase[(size_t)t * TAGq + tid] = mm;
        }
        __syncthreads();

        float* tp = cur; cur = nxt; nxt = tp;
        e = e_nxt;
    }
}

// ---------------------------------------------------------------------------
// Warp argmax over 256 values with jnp.argmax first-index semantics.
// Each lane contributes its local best (ascending strict-greater -> smallest
// local j). Cross-lane: redux-max on order key, then redux-min over winning
// lanes' indices -> global smallest j among maxima. Exact.
__device__ __forceinline__ int warp_argmax256(float xv, int xi, float* vmax_out) {
    unsigned kk   = okey(xv);
    unsigned kmax = __reduce_max_sync(0xffffffffu, kk);
    unsigned cand = (kk == kmax) ? (unsigned)xi : 0x7fffffffu;
    unsigned imin = __reduce_min_sync(0xffffffffu, cand);
    if (vmax_out) *vmax_out = okey_dec(kmax);
    return (int)imin;
}

// Backward: one CTA of 256 threads per batch. Warps 0..7 stage transT rows
// [0, CROWS) into SMEM; warp 0 then runs the sequential backtrace with
// bp recomputation (trans row from SMEM when cur < CROWS, else L2).
// Lane mapping (conflict-free & coalesced): lane owns f4 slots [lane] and
// [lane+32] of each 256-float row, i.e. j = 4*lane+k and 128+4*lane+k.
__global__ __launch_bounds__(256, 1)
void backward_kernel(const float* __restrict__ feats,
                     const int*   __restrict__ mask,
                     float*       __restrict__ out) {
    extern __shared__ float cache[];   // [CROWS][256]

    const int b = blockIdx.x;
    const int tid = threadIdx.x;

    // stage transT rows [0, CROWS)
    for (int idx = tid; idx < CROWS * 64; idx += 256)
        ((float4*)cache)[idx] = ((const float4*)g_transT)[idx];
    __syncthreads();

    if (tid >= 32) return;      // chain runs on warp 0 only
    const int lane = tid;

    // lengths = sum(mask[b,:])  (also warms the mask row into L1)
    int len = 0;
    for (int i = lane; i < Tq; i += 32) len += mask[b * Tq + i];
    #pragma unroll
    for (int o = 16; o; o >>= 1) len += __shfl_down_sync(0xffffffffu, len, o);
    len = __shfl_sync(0xffffffffu, len, 0);
    const int last = len - 1;

    const float* hb = g_hist + (size_t)b * Tq * TAGq;
    const int j0 = lane * 4;          // first-group base
    const int j1 = 128 + lane * 4;    // second-group base

    // path score / pointer: argmax_j last_part[j] + trans[j][STOP]
    int ptr;
    {
        const float4* lp4 = (const float4*)(hb + (size_t)last * TAGq);
        const float4* tc4 = (const float4*)(g_transT + STOP_TAG * TAGq);
        float4 A = lp4[lane], B = lp4[lane + 32];
        float4 C = tc4[lane], D = tc4[lane + 32];
        float v[8] = {A.x + C.x, A.y + C.y, A.z + C.z, A.w + C.w,
                      B.x + D.x, B.y + D.y, B.z + D.z, B.w + D.w};
        float xv = v[0]; int xi = j0;
        #pragma unroll
        for (int k = 1; k < 4; ++k)
            if (v[k] > xv) { xv = v[k]; xi = j0 + k; }
        #pragma unroll
        for (int k = 0; k < 4; ++k)
            if (v[4 + k] > xv) { xv = v[4 + k]; xi = j1 + k; }
        float bv;
        ptr = warp_argmax256(xv, xi, &bv);
        if (lane == 0) out[b] = bv;
    }

    float* dec = out + Bq;
    if (lane == 0) dec[(size_t)b * Tq + (Tq - 1)] = (float)ptr;

    const float4* cache4 = (const float4*)cache;

    int cur = ptr;
    for (int i = Tq - 2; i >= 0; --i) {
        // Prefetch-touch rows needed at iteration i-1 (index-predictable,
        // independent of cur): feats[b, i, :] and hist[b, i-1, :].
        {
            float d0;
            const float* fr = feats + ((size_t)b * Tq + i) * TAGq + lane * 8;
            asm volatile("ld.global.nc.f32 %0, [%1];" : "=f"(d0) : "l"(fr));
            if (i >= 1) {
                float d1;
                const float* hr = hb + (size_t)(i - 1) * TAGq + lane * 8;
                asm volatile("ld.global.nc.f32 %0, [%1];" : "=f"(d1) : "l"(hr));
            }
        }

        int nv;
        if (i == last) {
            nv = ptr;
        } else if (mask[b * Tq + i + 1] == 0) {
            nv = 0;
        } else {
            // recompute bp at time i+1, column cur — identical arithmetic
            // to the forward pass: (emit + trans) + part
            const float e =
                __ldg(feats + ((size_t)b * Tq + (i + 1)) * TAGq + cur);
            const float4* h4 = (const float4*)(hb + (size_t)i * TAGq);
            float4 H0 = h4[lane], H1 = h4[lane + 32];
            float4 T0, T1;
            if (cur < CROWS) {                    // warp-uniform branch
                T0 = cache4[cur * 64 + lane];
                T1 = cache4[cur * 64 + 32 + lane];
            } else {
                const float4* t4 = (const float4*)(g_transT + (size_t)cur * TAGq);
                T0 = t4[lane];
                T1 = t4[lane + 32];
            }
            float v[8] = {(e + T0.x) + H0.x, (e + T0.y) + H0.y,
                          (e + T0.z) + H0.z, (e + T0.w) + H0.w,
                          (e + T1.x) + H1.x, (e + T1.y) + H1.y,
                          (e + T1.z) + H1.z, (e + T1.w) + H1.w};
            float xv = v[0]; int xi = j0;
            #pragma unroll
            for (int k = 1; k < 4; ++k)
                if (v[k] > xv) { xv = v[k]; xi = j0 + k; }
            #pragma unroll
            for (int k = 0; k < 4; ++k)
                if (v[4 + k] > xv) { xv = v[4 + k]; xi = j1 + k; }
            nv = warp_argmax256(xv, xi, nullptr);
        }
        cur = nv;
        if (lane == 0) dec[(size_t)b * Tq + i] = (float)cur;
    }
}

// ---------------------------------------------------------------------------
extern "C" void kernel_launch(void* const* d_in, const int* in_sizes, int n_in,
                              void* d_out, int out_size) {
    const float* feats = (const float*)d_in[0];   // (128,512,256) f32
    const int*   mask  = (const int*)d_in[1];     // (128,512) i32
    const float* trans = (const float*)d_in[2];   // (256,256) f32
    float* out = (float*)d_out;                   // [128 path_score | 128*512 decode]

    transpose_kernel<<<TAGq, TAGq>>>(trans);

    const size_t smem_f =
        (size_t)(TAGq * TSTRIDE + 2 * TAGq + NTHREADS) * sizeof(float); // 139264 B
    cudaFuncSetAttribute(forward_kernel,
                         cudaFuncAttributeMaxDynamicSharedMemorySize, (int)smem_f);
    forward_kernel<<<Bq, NTHREADS, smem_f>>>(feats, trans);

    const size_t smem_b = (size_t)CROWS * TAGq * sizeof(float);        // 229376 B
    cudaFuncSetAttribute(backward_kernel,
                         cudaFuncAttributeMaxDynamicSharedMemorySize, (int)smem_b);
    backward_kernel<<<Bq, 256, smem_b>>>(feats, mask, out);
}